// round 12
// baseline (speedup 1.0000x reference)
#include <cuda_runtime.h>

#define IMG_SIZE 1280
#define NA 3
#define NC 80
#define BB 16
#define GG 160
#define CP 86              // 6 + NC
#define CC (NA * CP)       // 258
#define PLANE (GG * GG)    // 25600 floats per channel plane

#define NQUADS (BB * NA * PLANE / 4)   // 307200
#define THREADS 256

__device__ __forceinline__ float sigmoidf_(float v) {
    return 1.0f / (1.0f + expf(-v));
}

// One thread = 4 consecutive gx positions (float4 per channel plane).
// HIGH-WARP cell: __launch_bounds__(256, 6) caps regs at 42 -> 6 blocks/SM
// = 48 warps/SM. Body slimmed to fit: batch-2 / depth-2 argmax pipeline
// (a-pair comparing, b-pair in flight; 4 outstanding LDG.128 per thread,
// ~38 live regs). Box channels loaded after the argmax (no hoist: no spare
// regs in this regime).
__global__ __launch_bounds__(THREADS, 6) void anchor_decode_kernel(
    const float* __restrict__ x,
    const float* __restrict__ anchors,
    float* __restrict__ out)
{
    int tid = blockIdx.x * blockDim.x + threadIdx.x;
    if (tid >= NQUADS) return;

    const int quadsPerRow = GG / 4;           // 40
    int gx4  = (tid % quadsPerRow) * 4;
    int rest = tid / quadsPerRow;
    int gy   = rest % GG;
    int ba   = rest / GG;                     // b*NA + a
    int a    = ba % NA;
    int b    = ba / NA;

    const float* base = x + (size_t)(b * CC + a * CP) * PLANE + gy * GG + gx4;

    #define LD4(cp) (*reinterpret_cast<const float4*>(base + (size_t)(cp) * PLANE))

    // ---- Phase 1: argmax over 80 classes (channels 6..85) ----
    // first-max-wins: ascending class order + strict >.
    float bestv0 = -3.402823466e+38f, bestv1 = bestv0, bestv2 = bestv0, bestv3 = bestv0;
    float besti0 = 0.0f, besti1 = 0.0f, besti2 = 0.0f, besti3 = 0.0f;

    #define CMP(v, c) do {                                        \
        float fc_ = (float)(c);                                   \
        if ((v).x > bestv0) { bestv0 = (v).x; besti0 = fc_; }     \
        if ((v).y > bestv1) { bestv1 = (v).y; besti1 = fc_; }     \
        if ((v).z > bestv2) { bestv2 = (v).z; besti2 = fc_; }     \
        if ((v).w > bestv3) { bestv3 = (v).w; besti3 = fc_; }     \
    } while (0)

    // Depth-2, batch-2 pipeline: a = comparing now, b = in flight,
    // n = newly issued each iteration (prefetch distance 4 channels).
    float4 a0 = LD4(6 + 0), a1 = LD4(6 + 1);
    float4 b0 = LD4(6 + 2), b1 = LD4(6 + 3);

    #pragma unroll 2
    for (int c = 0; c < NC - 4; c += 2) {
        float4 n0 = LD4(6 + c + 4);
        float4 n1 = LD4(6 + c + 5);
        CMP(a0, c + 0);
        CMP(a1, c + 1);
        a0 = b0; a1 = b1;
        b0 = n0; b1 = n1;
    }
    // Tail: a holds classes NC-4, NC-3; b holds NC-2, NC-1.
    CMP(a0, NC - 4); CMP(a1, NC - 3);
    CMP(b0, NC - 2); CMP(b1, NC - 1);
    #undef CMP

    // ---- Phase 2: box channels (0..5), compute, store ----
    float4 vx   = LD4(0);
    float4 vy   = LD4(1);
    float4 vw   = LD4(2);
    float4 vh   = LD4(3);
    float4 vyaw = LD4(4);
    float4 vconf= LD4(5);
    #undef LD4

    const float stride = (float)IMG_SIZE / (float)GG;  // 8.0
    float aw = __ldg(&anchors[a * 2 + 0]);
    float ah = __ldg(&anchors[a * 2 + 1]);

    float ox[4]  = {vx.x, vx.y, vx.z, vx.w};
    float oy[4]  = {vy.x, vy.y, vy.z, vy.w};
    float ow[4]  = {vw.x, vw.y, vw.z, vw.w};
    float oh[4]  = {vh.x, vh.y, vh.z, vh.w};
    float oyw[4] = {vyaw.x, vyaw.y, vyaw.z, vyaw.w};
    float ocf[4] = {vconf.x, vconf.y, vconf.z, vconf.w};
    float bi[4]  = {besti0, besti1, besti2, besti3};

    float o[28];
    #pragma unroll
    for (int j = 0; j < 4; j++) {
        float sx = sigmoidf_(ox[j]);
        float sy = sigmoidf_(oy[j]);
        o[j * 7 + 0] = floorf((sx + (float)(gx4 + j)) * stride);
        o[j * 7 + 1] = floorf((sy + (float)gy) * stride);
        o[j * 7 + 2] = expf(ow[j]) * aw;
        o[j * 7 + 3] = expf(oh[j]) * ah;
        o[j * 7 + 4] = oyw[j];
        o[j * 7 + 5] = sigmoidf_(ocf[j]);
        o[j * 7 + 6] = bi[j];
    }

    // out offset = pos*7 floats, pos%4==0 -> 112B-aligned: 7 float4 stores.
    float* op = out + ((size_t)ba * PLANE + (size_t)gy * GG + gx4) * 7;
    float4* op4 = reinterpret_cast<float4*>(op);
    #pragma unroll
    for (int k = 0; k < 7; k++) {
        op4[k] = make_float4(o[k * 4 + 0], o[k * 4 + 1],
                             o[k * 4 + 2], o[k * 4 + 3]);
    }
}

extern "C" void kernel_launch(void* const* d_in, const int* in_sizes, int n_in,
                              void* d_out, int out_size) {
    const float* x       = (const float*)d_in[0];
    // d_in[1] = target (unused by reference output)
    const float* anchors = (const float*)d_in[2];
    float* out = (float*)d_out;

    const int blocks = (NQUADS + THREADS - 1) / THREADS;  // 1200
    anchor_decode_kernel<<<blocks, THREADS>>>(x, anchors, out);
}

// round 13
// speedup vs baseline: 1.1584x; 1.1584x over previous
#include <cuda_runtime.h>

#define IMG_SIZE 1280
#define NA 3
#define NC 80
#define BB 16
#define GG 160
#define CP 86              // 6 + NC
#define CC (NA * CP)       // 258
#define PLANE (GG * GG)    // 25600 floats per channel plane

#define NQUADS (BB * NA * PLANE / 4)   // 307200
#define THREADS 256

__device__ __forceinline__ float sigmoidf_(float v) {
    return 1.0f / (1.0f + expf(-v));
}

// Optimal cell (established over 12 rounds): 256 threads, 4 blocks/SM
// (64-reg pin), depth-1/batch-4 software-pipelined argmax, phase-ordered
// (argmax first), box loads hoisted over the tail compares. This round:
// epilogue writes computed directly as float4 (no 28-float staging array)
// to shorten epilogue live-ranges under the reg pin.
__global__ __launch_bounds__(THREADS, 4) void anchor_decode_kernel(
    const float* __restrict__ x,
    const float* __restrict__ anchors,
    float* __restrict__ out)
{
    int tid = blockIdx.x * blockDim.x + threadIdx.x;
    if (tid >= NQUADS) return;

    const int quadsPerRow = GG / 4;           // 40
    int gx4  = (tid % quadsPerRow) * 4;
    int rest = tid / quadsPerRow;
    int gy   = rest % GG;
    int ba   = rest / GG;                     // b*NA + a
    int a    = ba % NA;
    int b    = ba / NA;

    const float* base = x + (size_t)(b * CC + a * CP) * PLANE + gy * GG + gx4;

    #define LD4(cp) (*reinterpret_cast<const float4*>(base + (size_t)(cp) * PLANE))

    // ---- Phase 1: argmax over 80 classes (channels 6..85) ----
    // first-max-wins: ascending class order + strict >.
    float bestv0 = -3.402823466e+38f, bestv1 = bestv0, bestv2 = bestv0, bestv3 = bestv0;
    float besti0 = 0.0f, besti1 = 0.0f, besti2 = 0.0f, besti3 = 0.0f;

    #define CMP(v, c) do {                                        \
        float fc_ = (float)(c);                                   \
        if ((v).x > bestv0) { bestv0 = (v).x; besti0 = fc_; }     \
        if ((v).y > bestv1) { bestv1 = (v).y; besti1 = fc_; }     \
        if ((v).z > bestv2) { bestv2 = (v).z; besti2 = fc_; }     \
        if ((v).w > bestv3) { bestv3 = (v).w; besti3 = fc_; }     \
    } while (0)

    // Depth-1 software pipeline: load batch k+1 while comparing batch k.
    float4 cur0 = LD4(6 + 0);
    float4 cur1 = LD4(6 + 1);
    float4 cur2 = LD4(6 + 2);
    float4 cur3 = LD4(6 + 3);

    #pragma unroll 2
    for (int c = 0; c < NC - 4; c += 4) {
        float4 n0 = LD4(6 + c + 4);
        float4 n1 = LD4(6 + c + 5);
        float4 n2 = LD4(6 + c + 6);
        float4 n3 = LD4(6 + c + 7);
        CMP(cur0, c + 0);
        CMP(cur1, c + 1);
        CMP(cur2, c + 2);
        CMP(cur3, c + 3);
        cur0 = n0; cur1 = n1; cur2 = n2; cur3 = n3;
    }

    // Hoist phase-2 box loads so they fly during the tail compares.
    float4 vx   = LD4(0);
    float4 vy   = LD4(1);
    float4 vw   = LD4(2);
    float4 vh   = LD4(3);
    float4 vyaw = LD4(4);
    float4 vconf= LD4(5);

    CMP(cur0, NC - 4);
    CMP(cur1, NC - 3);
    CMP(cur2, NC - 2);
    CMP(cur3, NC - 1);
    #undef CMP
    #undef LD4

    // ---- Phase 2: compute + store directly (no staging array) ----
    const float stride = (float)IMG_SIZE / (float)GG;  // 8.0
    float aw = __ldg(&anchors[a * 2 + 0]);
    float ah = __ldg(&anchors[a * 2 + 1]);

    // Per-position values, position j in 0..3:
    // p0=floor((sig(x)+gx)*s), p1=floor((sig(y)+gy)*s), p2=exp(w)*aw,
    // p3=exp(h)*ah, p4=yaw, p5=sig(conf), p6=besti.
    float gyf = (float)gy;

    float p0_0 = floorf((sigmoidf_(vx.x) + (float)(gx4 + 0)) * stride);
    float p1_0 = floorf((sigmoidf_(vy.x) + gyf) * stride);
    float p2_0 = expf(vw.x) * aw;
    float p3_0 = expf(vh.x) * ah;
    float p5_0 = sigmoidf_(vconf.x);

    float p0_1 = floorf((sigmoidf_(vx.y) + (float)(gx4 + 1)) * stride);
    float p1_1 = floorf((sigmoidf_(vy.y) + gyf) * stride);
    float p2_1 = expf(vw.y) * aw;
    float p3_1 = expf(vh.y) * ah;
    float p5_1 = sigmoidf_(vconf.y);

    float p0_2 = floorf((sigmoidf_(vx.z) + (float)(gx4 + 2)) * stride);
    float p1_2 = floorf((sigmoidf_(vy.z) + gyf) * stride);
    float p2_2 = expf(vw.z) * aw;
    float p3_2 = expf(vh.z) * ah;
    float p5_2 = sigmoidf_(vconf.z);

    float p0_3 = floorf((sigmoidf_(vx.w) + (float)(gx4 + 3)) * stride);
    float p1_3 = floorf((sigmoidf_(vy.w) + gyf) * stride);
    float p2_3 = expf(vw.w) * aw;
    float p3_3 = expf(vh.w) * ah;
    float p5_3 = sigmoidf_(vconf.w);

    // out offset = pos*7 floats, pos%4==0 -> 112B-aligned: 7 float4 stores.
    // Layout of the 28 floats:
    //  [p0_0 p1_0 p2_0 p3_0][p4_0 p5_0 p6_0 p0_1][p1_1 p2_1 p3_1 p4_1]
    //  [p5_1 p6_1 p0_2 p1_2][p2_2 p3_2 p4_2 p5_2][p6_2 p0_3 p1_3 p2_3]
    //  [p3_3 p4_3 p5_3 p6_3]
    float* op = out + ((size_t)ba * PLANE + (size_t)gy * GG + gx4) * 7;
    float4* op4 = reinterpret_cast<float4*>(op);
    op4[0] = make_float4(p0_0, p1_0, p2_0, p3_0);
    op4[1] = make_float4(vyaw.x, p5_0, besti0, p0_1);
    op4[2] = make_float4(p1_1, p2_1, p3_1, vyaw.y);
    op4[3] = make_float4(p5_1, besti1, p0_2, p1_2);
    op4[4] = make_float4(p2_2, p3_2, vyaw.z, p5_2);
    op4[5] = make_float4(besti2, p0_3, p1_3, p2_3);
    op4[6] = make_float4(p3_3, vyaw.w, p5_3, besti3);
}

extern "C" void kernel_launch(void* const* d_in, const int* in_sizes, int n_in,
                              void* d_out, int out_size) {
    const float* x       = (const float*)d_in[0];
    // d_in[1] = target (unused by reference output)
    const float* anchors = (const float*)d_in[2];
    float* out = (float*)d_out;

    const int blocks = (NQUADS + THREADS - 1) / THREADS;  // 1200
    anchor_decode_kernel<<<blocks, THREADS>>>(x, anchors, out);
}

// round 14
// speedup vs baseline: 1.1769x; 1.0159x over previous
#include <cuda_runtime.h>

#define IMG_SIZE 1280
#define NA 3
#define NC 80
#define BB 16
#define GG 160
#define CP 86              // 6 + NC
#define CC (NA * CP)       // 258
#define PLANE (GG * GG)    // 25600 floats per channel plane

#define NQUADS (BB * NA * PLANE / 4)   // 307200
#define THREADS 256

__device__ __forceinline__ float sigmoidf_(float v) {
    return 1.0f / (1.0f + expf(-v));
}

// FINAL (best measured over 14 rounds): one thread = 4 consecutive gx
// positions (float4 per channel plane). 256 threads, __launch_bounds__(256,4)
// pins regs at 64 -> 4 blocks/SM = 32 warps/SM. Phase-ordered: argmax over
// the 80 class channels first with a depth-1/batch-4 software pipeline (the
// deepest pipeline that fits the reg pin without spilling), box-channel
// loads hoisted over the tail compares, epilogue after.
// Measured: 72.0us kernel, 6.17 TB/s, DRAM 77.9% — at this pattern's
// LTS-cap roofline. Deeper pipelines, more warps, fewer warps, persistence,
// wider blocks, and streaming hints all measured worse.
__global__ __launch_bounds__(THREADS, 4) void anchor_decode_kernel(
    const float* __restrict__ x,
    const float* __restrict__ anchors,
    float* __restrict__ out)
{
    int tid = blockIdx.x * blockDim.x + threadIdx.x;
    if (tid >= NQUADS) return;

    const int quadsPerRow = GG / 4;           // 40
    int gx4  = (tid % quadsPerRow) * 4;
    int rest = tid / quadsPerRow;
    int gy   = rest % GG;
    int ba   = rest / GG;                     // b*NA + a
    int a    = ba % NA;
    int b    = ba / NA;

    const float* base = x + (size_t)(b * CC + a * CP) * PLANE + gy * GG + gx4;

    #define LD4(cp) (*reinterpret_cast<const float4*>(base + (size_t)(cp) * PLANE))

    // ---- Phase 1: argmax over 80 classes (channels 6..85) ----
    // first-max-wins: ascending class order + strict >.
    float bestv0 = -3.402823466e+38f, bestv1 = bestv0, bestv2 = bestv0, bestv3 = bestv0;
    float besti0 = 0.0f, besti1 = 0.0f, besti2 = 0.0f, besti3 = 0.0f;

    #define CMP(v, c) do {                                        \
        float fc_ = (float)(c);                                   \
        if ((v).x > bestv0) { bestv0 = (v).x; besti0 = fc_; }     \
        if ((v).y > bestv1) { bestv1 = (v).y; besti1 = fc_; }     \
        if ((v).z > bestv2) { bestv2 = (v).z; besti2 = fc_; }     \
        if ((v).w > bestv3) { bestv3 = (v).w; besti3 = fc_; }     \
    } while (0)

    // Depth-1 software pipeline: load batch k+1 while comparing batch k.
    float4 cur0 = LD4(6 + 0);
    float4 cur1 = LD4(6 + 1);
    float4 cur2 = LD4(6 + 2);
    float4 cur3 = LD4(6 + 3);

    #pragma unroll 2
    for (int c = 0; c < NC - 4; c += 4) {
        float4 n0 = LD4(6 + c + 4);
        float4 n1 = LD4(6 + c + 5);
        float4 n2 = LD4(6 + c + 6);
        float4 n3 = LD4(6 + c + 7);
        CMP(cur0, c + 0);
        CMP(cur1, c + 1);
        CMP(cur2, c + 2);
        CMP(cur3, c + 3);
        cur0 = n0; cur1 = n1; cur2 = n2; cur3 = n3;
    }

    // Hoist phase-2 box loads so they fly during the tail compares.
    // Live here: cur(16) + box(24) + best(8) + addressing -> fits under 64.
    float4 vx   = LD4(0);
    float4 vy   = LD4(1);
    float4 vw   = LD4(2);
    float4 vh   = LD4(3);
    float4 vyaw = LD4(4);
    float4 vconf= LD4(5);

    CMP(cur0, NC - 4);
    CMP(cur1, NC - 3);
    CMP(cur2, NC - 2);
    CMP(cur3, NC - 1);
    #undef CMP
    #undef LD4

    // ---- Phase 2: compute + store ----
    const float stride = (float)IMG_SIZE / (float)GG;  // 8.0
    float aw = __ldg(&anchors[a * 2 + 0]);
    float ah = __ldg(&anchors[a * 2 + 1]);

    float ox[4]  = {vx.x, vx.y, vx.z, vx.w};
    float oy[4]  = {vy.x, vy.y, vy.z, vy.w};
    float ow[4]  = {vw.x, vw.y, vw.z, vw.w};
    float oh[4]  = {vh.x, vh.y, vh.z, vh.w};
    float oyw[4] = {vyaw.x, vyaw.y, vyaw.z, vyaw.w};
    float ocf[4] = {vconf.x, vconf.y, vconf.z, vconf.w};
    float bi[4]  = {besti0, besti1, besti2, besti3};

    float o[28];
    #pragma unroll
    for (int j = 0; j < 4; j++) {
        float sx = sigmoidf_(ox[j]);
        float sy = sigmoidf_(oy[j]);
        o[j * 7 + 0] = floorf((sx + (float)(gx4 + j)) * stride);
        o[j * 7 + 1] = floorf((sy + (float)gy) * stride);
        o[j * 7 + 2] = expf(ow[j]) * aw;
        o[j * 7 + 3] = expf(oh[j]) * ah;
        o[j * 7 + 4] = oyw[j];
        o[j * 7 + 5] = sigmoidf_(ocf[j]);
        o[j * 7 + 6] = bi[j];
    }

    // out offset = pos*7 floats, pos%4==0 -> 112B-aligned: 7 float4 stores.
    float* op = out + ((size_t)ba * PLANE + (size_t)gy * GG + gx4) * 7;
    float4* op4 = reinterpret_cast<float4*>(op);
    #pragma unroll
    for (int k = 0; k < 7; k++) {
        op4[k] = make_float4(o[k * 4 + 0], o[k * 4 + 1],
                             o[k * 4 + 2], o[k * 4 + 3]);
    }
}

extern "C" void kernel_launch(void* const* d_in, const int* in_sizes, int n_in,
                              void* d_out, int out_size) {
    const float* x       = (const float*)d_in[0];
    // d_in[1] = target (unused by reference output)
    const float* anchors = (const float*)d_in[2];
    float* out = (float*)d_out;

    const int blocks = (NQUADS + THREADS - 1) / THREADS;  // 1200
    anchor_decode_kernel<<<blocks, THREADS>>>(x, anchors, out);
}

// round 15
// speedup vs baseline: 1.1774x; 1.0004x over previous
#include <cuda_runtime.h>

#define IMG_SIZE 1280
#define NA 3
#define NC 80
#define BB 16
#define GG 160
#define CP 86              // 6 + NC
#define CC (NA * CP)       // 258
#define PLANE (GG * GG)    // 25600 floats per channel plane

#define NQUADS (BB * NA * PLANE / 4)   // 307200 == 1200 blocks * 256 threads
#define THREADS 256

__device__ __forceinline__ float sigmoidf_(float v) {
    return 1.0f / (1.0f + expf(-v));
}

// FINAL (converged over 15 rounds): one thread = 4 consecutive gx positions
// (float4 per channel plane). __launch_bounds__(256,4) pins regs at 64 ->
// 4 blocks/SM = 32 warps/SM. Phase-ordered: argmax over the 80 class
// channels first with a depth-1/batch-4 software pipeline (deepest that fits
// the reg pin without spilling), box loads hoisted over the tail compares.
// Grid covers NQUADS exactly (1200*256), so no bounds guard needed.
// Measured: 72.0-74.4us kernel, 6.0-6.17 TB/s — at this pattern's roofline.
__global__ __launch_bounds__(THREADS, 4) void anchor_decode_kernel(
    const float* __restrict__ x,
    const float* __restrict__ anchors,
    float* __restrict__ out)
{
    int tid = blockIdx.x * blockDim.x + threadIdx.x;   // < NQUADS by construction

    const int quadsPerRow = GG / 4;           // 40
    int gx4  = (tid % quadsPerRow) * 4;
    int rest = tid / quadsPerRow;
    int gy   = rest % GG;
    int ba   = rest / GG;                     // b*NA + a
    int a    = ba % NA;
    int b    = ba / NA;

    const float* base = x + (size_t)(b * CC + a * CP) * PLANE + gy * GG + gx4;

    #define LD4(cp) (*reinterpret_cast<const float4*>(base + (size_t)(cp) * PLANE))

    // ---- Phase 1: argmax over 80 classes (channels 6..85) ----
    // first-max-wins: ascending class order + strict >.
    float bestv0 = -3.402823466e+38f, bestv1 = bestv0, bestv2 = bestv0, bestv3 = bestv0;
    float besti0 = 0.0f, besti1 = 0.0f, besti2 = 0.0f, besti3 = 0.0f;

    #define CMP(v, c) do {                                        \
        float fc_ = (float)(c);                                   \
        if ((v).x > bestv0) { bestv0 = (v).x; besti0 = fc_; }     \
        if ((v).y > bestv1) { bestv1 = (v).y; besti1 = fc_; }     \
        if ((v).z > bestv2) { bestv2 = (v).z; besti2 = fc_; }     \
        if ((v).w > bestv3) { bestv3 = (v).w; besti3 = fc_; }     \
    } while (0)

    // Depth-1 software pipeline: load batch k+1 while comparing batch k.
    float4 cur0 = LD4(6 + 0);
    float4 cur1 = LD4(6 + 1);
    float4 cur2 = LD4(6 + 2);
    float4 cur3 = LD4(6 + 3);

    #pragma unroll 2
    for (int c = 0; c < NC - 4; c += 4) {
        float4 n0 = LD4(6 + c + 4);
        float4 n1 = LD4(6 + c + 5);
        float4 n2 = LD4(6 + c + 6);
        float4 n3 = LD4(6 + c + 7);
        CMP(cur0, c + 0);
        CMP(cur1, c + 1);
        CMP(cur2, c + 2);
        CMP(cur3, c + 3);
        cur0 = n0; cur1 = n1; cur2 = n2; cur3 = n3;
    }

    // Hoist phase-2 box loads so they fly during the tail compares.
    // Live here: cur(16) + box(24) + best(8) + addressing -> fits under 64.
    float4 vx   = LD4(0);
    float4 vy   = LD4(1);
    float4 vw   = LD4(2);
    float4 vh   = LD4(3);
    float4 vyaw = LD4(4);
    float4 vconf= LD4(5);

    CMP(cur0, NC - 4);
    CMP(cur1, NC - 3);
    CMP(cur2, NC - 2);
    CMP(cur3, NC - 1);
    #undef CMP
    #undef LD4

    // ---- Phase 2: compute + store ----
    const float stride = (float)IMG_SIZE / (float)GG;  // 8.0
    float aw = __ldg(&anchors[a * 2 + 0]);
    float ah = __ldg(&anchors[a * 2 + 1]);

    float ox[4]  = {vx.x, vx.y, vx.z, vx.w};
    float oy[4]  = {vy.x, vy.y, vy.z, vy.w};
    float ow[4]  = {vw.x, vw.y, vw.z, vw.w};
    float oh[4]  = {vh.x, vh.y, vh.z, vh.w};
    float oyw[4] = {vyaw.x, vyaw.y, vyaw.z, vyaw.w};
    float ocf[4] = {vconf.x, vconf.y, vconf.z, vconf.w};
    float bi[4]  = {besti0, besti1, besti2, besti3};

    float o[28];
    #pragma unroll
    for (int j = 0; j < 4; j++) {
        float sx = sigmoidf_(ox[j]);
        float sy = sigmoidf_(oy[j]);
        o[j * 7 + 0] = floorf((sx + (float)(gx4 + j)) * stride);
        o[j * 7 + 1] = floorf((sy + (float)gy) * stride);
        o[j * 7 + 2] = expf(ow[j]) * aw;
        o[j * 7 + 3] = expf(oh[j]) * ah;
        o[j * 7 + 4] = oyw[j];
        o[j * 7 + 5] = sigmoidf_(ocf[j]);
        o[j * 7 + 6] = bi[j];
    }

    // out offset = pos*7 floats, pos%4==0 -> 112B-aligned: 7 float4 stores.
    float* op = out + ((size_t)ba * PLANE + (size_t)gy * GG + gx4) * 7;
    float4* op4 = reinterpret_cast<float4*>(op);
    #pragma unroll
    for (int k = 0; k < 7; k++) {
        op4[k] = make_float4(o[k * 4 + 0], o[k * 4 + 1],
                             o[k * 4 + 2], o[k * 4 + 3]);
    }
}

extern "C" void kernel_launch(void* const* d_in, const int* in_sizes, int n_in,
                              void* d_out, int out_size) {
    const float* x       = (const float*)d_in[0];
    // d_in[1] = target (unused by reference output)
    const float* anchors = (const float*)d_in[2];
    float* out = (float*)d_out;

    const int blocks = NQUADS / THREADS;   // exactly 1200
    anchor_decode_kernel<<<blocks, THREADS>>>(x, anchors, out);
}